// round 16
// baseline (speedup 1.0000x reference)
#include <cuda_runtime.h>
#include <cuda_fp16.h>
#include <cstdint>
#include <math.h>

#define N_ROWS 8192
#define DIM    256
#define CPAD   8320                 /* compacted capacity: 8192 + 128 pad */
#define SCALE  28.85390081777927f   /* (1/0.05) * log2(e) */
#define LN2F   0.6931471805599453f
#define SKIPV  (-2147483647 - 1)    /* INT_MIN: invalid row, no pad slot */

#define BM     64       /* rows per CTA band (compacted) */
#define BN     128      /* cols per tile (compacted) */
#define KC     64
#define NCH    4        /* column interleave factor */
#define GRID_MAIN 512

#define SM_A     0            /* 32 KB: 4 k-chunks x [64 rows x 128B] */
#define SM_B     32768        /* 4 ring slots x 16 KB */
#define B_SLOT   16384
#define SM_ADV   98304        /* 128 ints */
#define SM_REDA  98816        /* 256 floats */
#define SM_REDP  99840        /* 256 floats */
#define DSMEM_BYTES 100864

// ---------------- device scratch ---------------------------------------------
__device__ __half g_qc[CPAD * DIM];     // compacted, q scaled by SCALE
__device__ __half g_kc[CPAD * DIM];     // compacted
__device__ int   g_cadv[CPAD];          // compacted ad (valid rows), -1 in pad
__device__ int   g_cidx[N_ROWS];        // fused code: j / ~(cnt+i) / INT_MIN
__device__ int   g_cnt;                 // number of valid rows
__device__ float g_rowAP[CPAD * 8];     // per row: [A0,A1,A2,A3,P0,P1,P2,P3]
__device__ int   g_done;                // CTA arrival counter (reset each call)

// ---------------- PTX helpers ------------------------------------------------
__device__ __forceinline__ uint32_t smem_u32(const void* p) {
    uint32_t a;
    asm("{ .reg .u64 t; cvta.to.shared.u64 t, %1; cvt.u32.u64 %0, t; }" : "=r"(a) : "l"(p));
    return a;
}
__device__ __forceinline__ float fast_exp2(float x) {
    float y; asm("ex2.approx.ftz.f32 %0, %1;" : "=f"(y) : "f"(x)); return y;
}
#define CPA(dst, src) \
    asm volatile("cp.async.cg.shared.global [%0], [%1], 16;" :: "r"(dst), "l"(src) : "memory")
#define CPC()  asm volatile("cp.async.commit_group;" ::: "memory")
#define CPW2() asm volatile("cp.async.wait_group 2;" ::: "memory")
#define CPW1() asm volatile("cp.async.wait_group 1;" ::: "memory")
#define CPW0() asm volatile("cp.async.wait_group 0;" ::: "memory")

#define LDSM4(r, a) \
    asm volatile("ldmatrix.sync.aligned.m8n8.x4.shared.b16 {%0,%1,%2,%3}, [%4];" \
                 : "=r"((r)[0]), "=r"((r)[1]), "=r"((r)[2]), "=r"((r)[3]) : "r"(a))

#define MMA16816(d, a, b0, b1) \
    asm volatile("mma.sync.aligned.m16n8k16.row.col.f32.f16.f16.f32 " \
                 "{%0,%1,%2,%3}, {%4,%5,%6,%7}, {%8,%9}, {%0,%1,%2,%3};" \
                 : "+f"((d)[0]), "+f"((d)[1]), "+f"((d)[2]), "+f"((d)[3]) \
                 : "r"((a)[0]), "r"((a)[1]), "r"((a)[2]), "r"((a)[3]), \
                   "r"(b0), "r"(b1))

// ---------------- kernel 1: validity scan (fused code word) ------------------
__global__ void scan_kernel(const int* __restrict__ pad) {
    const int t = threadIdx.x;        // 1024
    const int lane = t & 31, warp = t >> 5;
    if (t == 0) g_done = 0;           // reset finisher counter every call
    int4 a = reinterpret_cast<const int4*>(pad)[2 * t];
    int4 b = reinterpret_cast<const int4*>(pad)[2 * t + 1];
    int v[8] = {a.x ? 1 : 0, a.y ? 1 : 0, a.z ? 1 : 0, a.w ? 1 : 0,
                b.x ? 1 : 0, b.y ? 1 : 0, b.z ? 1 : 0, b.w ? 1 : 0};
    int pre[8], s = 0;
#pragma unroll
    for (int i = 0; i < 8; i++) { pre[i] = s; s += v[i]; }
    int incl = s;
#pragma unroll
    for (int o = 1; o < 32; o <<= 1) {
        int n = __shfl_up_sync(0xffffffffu, incl, o);
        if (lane >= o) incl += n;
    }
    __shared__ int wtot[32], woff[32], s_tot;
    if (lane == 31) wtot[warp] = incl;
    __syncthreads();
    if (t < 32) {
        int w = wtot[t], wi = w;
#pragma unroll
        for (int o = 1; o < 32; o <<= 1) {
            int n = __shfl_up_sync(0xffffffffu, wi, o);
            if (t >= o) wi += n;
        }
        woff[t] = wi - w;
        if (t == 31) { g_cnt = wi; s_tot = wi; }
    }
    __syncthreads();
    const int cnt = s_tot;
    int base = woff[warp] + incl - s;
#pragma unroll
    for (int i = 0; i < 8; i++) {
        int row = 8 * t + i;
        int j = base + pre[i];        // exclusive valid prefix
        int inv = row - j;            // exclusive invalid prefix
        g_cidx[row] = v[i] ? j : ((inv < 128) ? ~(cnt + inv) : SKIPV);
    }
}

// ---------------- kernel 2: normalize + scatter (single index load) ----------
__global__ void scatter_kernel(const float* __restrict__ logits,
                               const float* __restrict__ labels,
                               const int* __restrict__ ad) {
    const int lane = threadIdx.x & 31;
    const int warp = threadIdx.x >> 5;
    const int row  = blockIdx.x * 8 + warp;
    const int c = g_cidx[row];
    if (c >= 0) {
        const float* src = blockIdx.y ? labels : logits;
        __half* dst = blockIdx.y ? g_kc : g_qc;
        const float post = blockIdx.y ? 1.0f : SCALE;
        const float* rp = src + (size_t)row * DIM + lane * 8;
        float4 v0 = *reinterpret_cast<const float4*>(rp);
        float4 v1 = *reinterpret_cast<const float4*>(rp + 4);
        float ss = v0.x*v0.x + v0.y*v0.y + v0.z*v0.z + v0.w*v0.w
                 + v1.x*v1.x + v1.y*v1.y + v1.z*v1.z + v1.w*v1.w;
#pragma unroll
        for (int o = 16; o; o >>= 1) ss += __shfl_xor_sync(0xffffffffu, ss, o);
        float s = (1.0f / fmaxf(sqrtf(ss), 1e-12f)) * post;
        __half2 h0 = __floats2half2_rn(v0.x * s, v0.y * s);
        __half2 h1 = __floats2half2_rn(v0.z * s, v0.w * s);
        __half2 h2 = __floats2half2_rn(v1.x * s, v1.y * s);
        __half2 h3 = __floats2half2_rn(v1.z * s, v1.w * s);
        uint4 pk;
        pk.x = *reinterpret_cast<uint32_t*>(&h0);
        pk.y = *reinterpret_cast<uint32_t*>(&h1);
        pk.z = *reinterpret_cast<uint32_t*>(&h2);
        pk.w = *reinterpret_cast<uint32_t*>(&h3);
        *reinterpret_cast<uint4*>(dst + (size_t)c * DIM + lane * 8) = pk;
        if (blockIdx.y == 0 && lane == 0) g_cadv[c] = ad[row];
    } else if (c != SKIPV) {
        const int j = ~c;            // pad slot cnt + i
        __half* dst = blockIdx.y ? g_kc : g_qc;
        const uint4 z = {0u, 0u, 0u, 0u};
        *reinterpret_cast<uint4*>(dst + (size_t)j * DIM + lane * 8) = z;
        if (blockIdx.y == 0 && lane == 0) g_cadv[j] = -1;
    }
}

// ---------------- B chunk issue (cp.async, swizzled) --------------------------
__device__ __forceinline__ void issue_b(uint32_t smb, int l, int ch, int tid) {
    const int tile = ch + ((l >> 2) << 2);       // ch, ch+4, ch+8, ...
    const int col0 = tile * BN;
    const int koff = (l & 3) * KC;
    uint32_t slot = smb + SM_B + (uint32_t)(l & 3) * B_SLOT;
#pragma unroll
    for (int r = 0; r < 4; r++) {
        int idx = r * 256 + tid;
        int n = idx >> 3;
        int g = idx & 7;
        uint32_t dst = slot + (uint32_t)(n * 128 + ((g ^ (n & 7)) << 4));
        CPA(dst, g_kc + (size_t)(col0 + n) * DIM + koff + g * 8);
    }
    CPC();
}

// ---------------- kernel 3: fused GEMM + masked-exp + global finisher --------
__global__ __launch_bounds__(256, 2) void main_kernel(float* __restrict__ out) {
    extern __shared__ char dsm[];
    const uint32_t smb = smem_u32(dsm);
    const int tid  = threadIdx.x;
    const int lane = tid & 31;
    const int wid  = tid >> 5;
    const int wm   = wid >> 2;        // 0..1 (32-row half of 64)
    const int wn   = wid & 3;         // 0..3 (32-col quarter of 128)
    const int band = blockIdx.x >> 2;
    const int ch   = blockIdx.x & 3;
    const int brow = band * BM;
    const int cnt  = g_cnt;

    int*   advT = reinterpret_cast<int*>(dsm + SM_ADV);
    float* redA = reinterpret_cast<float*>(dsm + SM_REDA);
    float* redP = reinterpret_cast<float*>(dsm + SM_REDP);
    __shared__ int s_last;

    if (brow < cnt) {
        const int T   = (cnt + 127) >> 7;
        const int myT = (T - ch + 3) >> 2;
        if (myT > 0) {
            const int NC = 4 * myT;

            const int matA = lane >> 3;
            const int rowAoff = (lane & 7) + ((matA & 1) << 3);
            const int khA  = matA >> 1;
            const int nrowOff = ((lane >> 4) << 3) + (lane & 7);
            const int khB  = (lane >> 3) & 1;

            uint32_t aRowByte[2]; int aRowX[2];
#pragma unroll
            for (int mi = 0; mi < 2; mi++) {
                int row = wm * 32 + mi * 16 + rowAoff;
                aRowByte[mi] = (uint32_t)(row * 128);
                aRowX[mi] = row & 7;
            }
            uint32_t bRowByte[2]; int bRowX[2];
#pragma unroll
            for (int nj = 0; nj < 2; nj++) {
                int nrow = wn * 32 + nj * 16 + nrowOff;
                bRowByte[nj] = (uint32_t)(nrow * 128);
                bRowX[nj] = nrow & 7;
            }

            int adiR[2][2];
#pragma unroll
            for (int mi = 0; mi < 2; mi++)
#pragma unroll
                for (int h = 0; h < 2; h++)
                    adiR[mi][h] = g_cadv[brow + wm * 32 + mi * 16 + h * 8 + (lane >> 2)];

            // ---- prologue: A band (32 KB), then B chunks 0,1 ----
#pragma unroll
            for (int r = 0; r < 8; r++) {
                int idx = r * 256 + tid;
                int m = idx >> 5;
                int g = idx & 31;
                uint32_t dst = smb + SM_A + (uint32_t)((g >> 3) * 8192 + m * 128 +
                                                       (((g & 7) ^ (m & 7)) << 4));
                CPA(dst, g_qc + (size_t)(brow + m) * DIM + g * 8);
            }
            CPC();
            issue_b(smb, 0, ch, tid);
            issue_b(smb, 1, ch, tid);

            float sA[2][2], sP[2][2];
#pragma unroll
            for (int mi = 0; mi < 2; mi++)
#pragma unroll
                for (int h = 0; h < 2; h++) { sA[mi][h] = 0.f; sP[mi][h] = 0.f; }

#pragma unroll 1
            for (int tloc = 0; tloc < myT; tloc++) {
                float acc[2][4][4];
#pragma unroll
                for (int mi = 0; mi < 2; mi++)
#pragma unroll
                    for (int n8 = 0; n8 < 4; n8++)
#pragma unroll
                        for (int r = 0; r < 4; r++) acc[mi][n8][r] = 0.f;

#pragma unroll
                for (int kc = 0; kc < 4; kc++) {
                    const int l = tloc * 4 + kc;
                    if (l + 2 < NC) { issue_b(smb, l + 2, ch, tid); CPW2(); }
                    else if (l + 2 == NC) { CPW1(); }
                    else { CPW0(); }
                    __syncthreads();
                    if (kc == 0 && tid < BN)
                        advT[tid] = g_cadv[(ch + 4 * tloc) * BN + tid];

                    const uint32_t aC = smb + SM_A + (uint32_t)kc * 8192;
                    const uint32_t bB = smb + SM_B + (uint32_t)(l & 3) * B_SLOT;
#pragma unroll
                    for (int s = 0; s < 4; s++) {
                        uint32_t af[2][4], bf[2][4];
#pragma unroll
                        for (int mi = 0; mi < 2; mi++) {
                            uint32_t gr = (uint32_t)(((s * 2 + khA) ^ aRowX[mi]) << 4);
                            LDSM4(af[mi], aC + aRowByte[mi] + gr);
                        }
#pragma unroll
                        for (int nj = 0; nj < 2; nj++) {
                            uint32_t gr = (uint32_t)(((s * 2 + khB) ^ bRowX[nj]) << 4);
                            LDSM4(bf[nj], bB + bRowByte[nj] + gr);
                        }
#pragma unroll
                        for (int mi = 0; mi < 2; mi++)
#pragma unroll
                            for (int n8 = 0; n8 < 4; n8++)
                                MMA16816(acc[mi][n8], af[mi],
                                         bf[n8 >> 1][(n8 & 1) * 2],
                                         bf[n8 >> 1][(n8 & 1) * 2 + 1]);
                    }
                }

                // ---- epilogue (32 EX2/thread) ----
#pragma unroll
                for (int n8 = 0; n8 < 4; n8++) {
                    const int nb = wn * 32 + n8 * 8 + (lane & 3) * 2;
                    const int a0 = advT[nb], a1 = advT[nb + 1];
#pragma unroll
                    for (int mi = 0; mi < 2; mi++)
#pragma unroll
                        for (int h = 0; h < 2; h++) {
                            float e0 = fast_exp2(acc[mi][n8][h * 2]);
                            float e1 = fast_exp2(acc[mi][n8][h * 2 + 1]);
                            if (a0 >= 0) sA[mi][h] += e0;
                            if (a1 >= 0) sA[mi][h] += e1;
                            if (a0 == adiR[mi][h]) sP[mi][h] += e0;
                            if (a1 == adiR[mi][h]) sP[mi][h] += e1;
                        }
                }
            }

            // ---- reduce over lane&3, then across wn warps ----
#pragma unroll
            for (int mi = 0; mi < 2; mi++)
#pragma unroll
                for (int h = 0; h < 2; h++) {
#pragma unroll
                    for (int o = 1; o < 4; o <<= 1) {
                        sA[mi][h] += __shfl_xor_sync(0xffffffffu, sA[mi][h], o);
                        sP[mi][h] += __shfl_xor_sync(0xffffffffu, sP[mi][h], o);
                    }
                }
            if ((lane & 3) == 0) {
#pragma unroll
                for (int mi = 0; mi < 2; mi++)
#pragma unroll
                    for (int h = 0; h < 2; h++) {
                        int rl = wm * 32 + mi * 16 + h * 8 + (lane >> 2);
                        redA[wn * 64 + rl] = sA[mi][h];
                        redP[wn * 64 + rl] = sP[mi][h];
                    }
            }
            __syncthreads();
            if (tid < BM) {
                float A = redA[tid] + redA[64 + tid] + redA[128 + tid] + redA[192 + tid];
                float P = redP[tid] + redP[64 + tid] + redP[128 + tid] + redP[192 + tid];
                g_rowAP[(size_t)(brow + tid) * 8 + ch] = A;
                g_rowAP[(size_t)(brow + tid) * 8 + 4 + ch] = P;
            }
        } else {
            if (tid < BM) {
                g_rowAP[(size_t)(brow + tid) * 8 + ch] = 0.f;
                g_rowAP[(size_t)(brow + tid) * 8 + 4 + ch] = 0.f;
            }
        }
    }

    // ---- global finisher: last of all 512 CTAs reduces the loss -------------
    __syncthreads();
    if (tid == 0) {
        __threadfence();                                     // release rowAP
        s_last = (atomicAdd(&g_done, 1) == GRID_MAIN - 1);
    }
    __syncthreads();
    if (s_last) {
        if (tid == 0) __threadfence();                       // acquire
        __syncthreads();
        float l = 0.f;
        for (int j = tid; j < cnt; j += 256) {
            float4 a = *reinterpret_cast<const float4*>(g_rowAP + (size_t)j * 8);
            float4 p = *reinterpret_cast<const float4*>(g_rowAP + (size_t)j * 8 + 4);
            float A = (a.x + a.y) + (a.z + a.w);
            float P = (p.x + p.y) + (p.z + p.w);
            l += (log2f(A) - log2f(P)) * LN2F;
        }
#pragma unroll
        for (int o = 16; o; o >>= 1) l += __shfl_xor_sync(0xffffffffu, l, o);
        if (lane == 0) redA[wid] = l;
        __syncthreads();
        if (tid == 0) {
            float tot = 0.f;
#pragma unroll
            for (int w = 0; w < 8; w++) tot += redA[w];
            out[0] = tot / fmaxf((float)cnt, 1.0f);
        }
    }
}

// ---------------- launch ------------------------------------------------------
extern "C" void kernel_launch(void* const* d_in, const int* in_sizes, int n_in,
                              void* d_out, int out_size) {
    const float* logits = (const float*)d_in[0];
    const float* labels = (const float*)d_in[1];
    const int*   pad    = (const int*)d_in[2];
    const int*   ad     = (const int*)d_in[3];

    cudaFuncSetAttribute(main_kernel, cudaFuncAttributeMaxDynamicSharedMemorySize,
                         DSMEM_BYTES);

    scan_kernel<<<1, 1024>>>(pad);
    scatter_kernel<<<dim3(1024, 2), 256>>>(logits, labels, ad);
    main_kernel<<<GRID_MAIN, 256, DSMEM_BYTES>>>((float*)d_out);
}

// round 17
// speedup vs baseline: 1.1372x; 1.1372x over previous
#include <cuda_runtime.h>
#include <cuda_fp16.h>
#include <cstdint>
#include <math.h>

#define N_ROWS 8192
#define DIM    256
#define CPAD   8320                 /* compacted capacity: 8192 + 128 pad */
#define SCALE  28.85390081777927f   /* (1/0.05) * log2(e) */
#define LN2F   0.6931471805599453f
#define SKIPV  (-2147483647 - 1)    /* INT_MIN: invalid row, no pad slot */

#define BM     64       /* rows per CTA band (compacted) */
#define BN     128      /* cols per tile (compacted) */
#define KC     64
#define NCH    4        /* column interleave factor */

#define SM_A     0            /* 32 KB: 4 k-chunks x [64 rows x 128B] */
#define SM_B     32768        /* 4 ring slots x 16 KB */
#define B_SLOT   16384
#define SM_ADV   98304        /* 128 ints */
#define SM_REDA  98816        /* 256 floats */
#define SM_REDP  99840        /* 256 floats */
#define DSMEM_BYTES 100864

// ---------------- device scratch ---------------------------------------------
__device__ __half g_qc[CPAD * DIM];     // compacted, q scaled by SCALE
__device__ __half g_kc[CPAD * DIM];     // compacted
__device__ int   g_cadv[CPAD];          // compacted ad (valid rows), -1 in pad
__device__ int   g_cidx[N_ROWS];        // fused code: j / ~(cnt+i) / INT_MIN
__device__ int   g_cnt;                 // number of valid rows
__device__ float g_rowAP[CPAD * 8];     // per row: [A0,A1,A2,A3,P0,P1,P2,P3]

// ---------------- PTX helpers ------------------------------------------------
__device__ __forceinline__ uint32_t smem_u32(const void* p) {
    uint32_t a;
    asm("{ .reg .u64 t; cvta.to.shared.u64 t, %1; cvt.u32.u64 %0, t; }" : "=r"(a) : "l"(p));
    return a;
}
__device__ __forceinline__ float fast_exp2(float x) {
    float y; asm("ex2.approx.ftz.f32 %0, %1;" : "=f"(y) : "f"(x)); return y;
}
#define CPA(dst, src) \
    asm volatile("cp.async.cg.shared.global [%0], [%1], 16;" :: "r"(dst), "l"(src) : "memory")
#define CPC()  asm volatile("cp.async.commit_group;" ::: "memory")
#define CPW2() asm volatile("cp.async.wait_group 2;" ::: "memory")
#define CPW1() asm volatile("cp.async.wait_group 1;" ::: "memory")
#define CPW0() asm volatile("cp.async.wait_group 0;" ::: "memory")

#define LDSM4(r, a) \
    asm volatile("ldmatrix.sync.aligned.m8n8.x4.shared.b16 {%0,%1,%2,%3}, [%4];" \
                 : "=r"((r)[0]), "=r"((r)[1]), "=r"((r)[2]), "=r"((r)[3]) : "r"(a))

#define MMA16816(d, a, b0, b1) \
    asm volatile("mma.sync.aligned.m16n8k16.row.col.f32.f16.f16.f32 " \
                 "{%0,%1,%2,%3}, {%4,%5,%6,%7}, {%8,%9}, {%0,%1,%2,%3};" \
                 : "+f"((d)[0]), "+f"((d)[1]), "+f"((d)[2]), "+f"((d)[3]) \
                 : "r"((a)[0]), "r"((a)[1]), "r"((a)[2]), "r"((a)[3]), \
                   "r"(b0), "r"(b1))

// ---------------- kernel 1: validity scan (fused code word) ------------------
__global__ void scan_kernel(const int* __restrict__ pad) {
    const int t = threadIdx.x;        // 1024
    const int lane = t & 31, warp = t >> 5;
    int4 a = reinterpret_cast<const int4*>(pad)[2 * t];
    int4 b = reinterpret_cast<const int4*>(pad)[2 * t + 1];
    int v[8] = {a.x ? 1 : 0, a.y ? 1 : 0, a.z ? 1 : 0, a.w ? 1 : 0,
                b.x ? 1 : 0, b.y ? 1 : 0, b.z ? 1 : 0, b.w ? 1 : 0};
    int pre[8], s = 0;
#pragma unroll
    for (int i = 0; i < 8; i++) { pre[i] = s; s += v[i]; }
    int incl = s;
#pragma unroll
    for (int o = 1; o < 32; o <<= 1) {
        int n = __shfl_up_sync(0xffffffffu, incl, o);
        if (lane >= o) incl += n;
    }
    __shared__ int wtot[32], woff[32], s_tot;
    if (lane == 31) wtot[warp] = incl;
    __syncthreads();
    if (t < 32) {
        int w = wtot[t], wi = w;
#pragma unroll
        for (int o = 1; o < 32; o <<= 1) {
            int n = __shfl_up_sync(0xffffffffu, wi, o);
            if (t >= o) wi += n;
        }
        woff[t] = wi - w;
        if (t == 31) { g_cnt = wi; s_tot = wi; }
    }
    __syncthreads();
    const int cnt = s_tot;
    int base = woff[warp] + incl - s;
#pragma unroll
    for (int i = 0; i < 8; i++) {
        int row = 8 * t + i;
        int j = base + pre[i];        // exclusive valid prefix
        int inv = row - j;            // exclusive invalid prefix
        g_cidx[row] = v[i] ? j : ((inv < 128) ? ~(cnt + inv) : SKIPV);
    }
}

// ---------------- kernel 2: normalize + scatter (single index load) ----------
__global__ void scatter_kernel(const float* __restrict__ logits,
                               const float* __restrict__ labels,
                               const int* __restrict__ ad) {
    const int lane = threadIdx.x & 31;
    const int warp = threadIdx.x >> 5;
    const int row  = blockIdx.x * 8 + warp;
    const int c = g_cidx[row];
    if (c >= 0) {
        const float* src = blockIdx.y ? labels : logits;
        __half* dst = blockIdx.y ? g_kc : g_qc;
        const float post = blockIdx.y ? 1.0f : SCALE;
        const float* rp = src + (size_t)row * DIM + lane * 8;
        float4 v0 = *reinterpret_cast<const float4*>(rp);
        float4 v1 = *reinterpret_cast<const float4*>(rp + 4);
        float ss = v0.x*v0.x + v0.y*v0.y + v0.z*v0.z + v0.w*v0.w
                 + v1.x*v1.x + v1.y*v1.y + v1.z*v1.z + v1.w*v1.w;
#pragma unroll
        for (int o = 16; o; o >>= 1) ss += __shfl_xor_sync(0xffffffffu, ss, o);
        float s = (1.0f / fmaxf(sqrtf(ss), 1e-12f)) * post;
        __half2 h0 = __floats2half2_rn(v0.x * s, v0.y * s);
        __half2 h1 = __floats2half2_rn(v0.z * s, v0.w * s);
        __half2 h2 = __floats2half2_rn(v1.x * s, v1.y * s);
        __half2 h3 = __floats2half2_rn(v1.z * s, v1.w * s);
        uint4 pk;
        pk.x = *reinterpret_cast<uint32_t*>(&h0);
        pk.y = *reinterpret_cast<uint32_t*>(&h1);
        pk.z = *reinterpret_cast<uint32_t*>(&h2);
        pk.w = *reinterpret_cast<uint32_t*>(&h3);
        *reinterpret_cast<uint4*>(dst + (size_t)c * DIM + lane * 8) = pk;
        if (blockIdx.y == 0 && lane == 0) g_cadv[c] = ad[row];
    } else if (c != SKIPV) {
        const int j = ~c;            // pad slot cnt + i
        __half* dst = blockIdx.y ? g_kc : g_qc;
        const uint4 z = {0u, 0u, 0u, 0u};
        *reinterpret_cast<uint4*>(dst + (size_t)j * DIM + lane * 8) = z;
        if (blockIdx.y == 0 && lane == 0) g_cadv[j] = -1;
    }
}

// ---------------- B chunk issue (cp.async, swizzled) --------------------------
__device__ __forceinline__ void issue_b(uint32_t smb, int l, int ch, int tid) {
    const int tile = ch + ((l >> 2) << 2);       // ch, ch+4, ch+8, ...
    const int col0 = tile * BN;
    const int koff = (l & 3) * KC;
    uint32_t slot = smb + SM_B + (uint32_t)(l & 3) * B_SLOT;
#pragma unroll
    for (int r = 0; r < 4; r++) {
        int idx = r * 256 + tid;
        int n = idx >> 3;
        int g = idx & 7;
        uint32_t dst = slot + (uint32_t)(n * 128 + ((g ^ (n & 7)) << 4));
        CPA(dst, g_kc + (size_t)(col0 + n) * DIM + koff + g * 8);
    }
    CPC();
}

// ---------------- kernel 3: fused compacted GEMM + masked-exp ----------------
__global__ __launch_bounds__(256, 2) void main_kernel() {
    extern __shared__ char dsm[];
    const uint32_t smb = smem_u32(dsm);
    const int tid  = threadIdx.x;
    const int lane = tid & 31;
    const int wid  = tid >> 5;
    const int wm   = wid >> 2;        // 0..1 (32-row half of 64)
    const int wn   = wid & 3;         // 0..3 (32-col quarter of 128)
    const int band = blockIdx.x >> 2;
    const int ch   = blockIdx.x & 3;
    const int brow = band * BM;
    const int cnt  = g_cnt;
    if (brow >= cnt) return;
    const int T   = (cnt + 127) >> 7;
    const int myT = (T - ch + 3) >> 2;
    if (myT == 0) {
        if (tid < BM) {
            g_rowAP[(size_t)(brow + tid) * 8 + ch] = 0.f;
            g_rowAP[(size_t)(brow + tid) * 8 + 4 + ch] = 0.f;
        }
        return;
    }
    const int NC = 4 * myT;

    int*   advT = reinterpret_cast<int*>(dsm + SM_ADV);
    float* redA = reinterpret_cast<float*>(dsm + SM_REDA);
    float* redP = reinterpret_cast<float*>(dsm + SM_REDP);

    const int matA = lane >> 3;
    const int rowAoff = (lane & 7) + ((matA & 1) << 3);
    const int khA  = matA >> 1;
    const int nrowOff = ((lane >> 4) << 3) + (lane & 7);
    const int khB  = (lane >> 3) & 1;

    uint32_t aRowByte[2]; int aRowX[2];
#pragma unroll
    for (int mi = 0; mi < 2; mi++) {
        int row = wm * 32 + mi * 16 + rowAoff;
        aRowByte[mi] = (uint32_t)(row * 128);
        aRowX[mi] = row & 7;
    }
    uint32_t bRowByte[2]; int bRowX[2];
#pragma unroll
    for (int nj = 0; nj < 2; nj++) {
        int nrow = wn * 32 + nj * 16 + nrowOff;
        bRowByte[nj] = (uint32_t)(nrow * 128);
        bRowX[nj] = nrow & 7;
    }

    int adiR[2][2];
#pragma unroll
    for (int mi = 0; mi < 2; mi++)
#pragma unroll
        for (int h = 0; h < 2; h++)
            adiR[mi][h] = g_cadv[brow + wm * 32 + mi * 16 + h * 8 + (lane >> 2)];

    // ---- prologue: A band (32 KB), then B chunks 0,1 ----
#pragma unroll
    for (int r = 0; r < 8; r++) {
        int idx = r * 256 + tid;
        int m = idx >> 5;          // row 0..63
        int g = idx & 31;          // 16B granule
        uint32_t dst = smb + SM_A + (uint32_t)((g >> 3) * 8192 + m * 128 +
                                               (((g & 7) ^ (m & 7)) << 4));
        CPA(dst, g_qc + (size_t)(brow + m) * DIM + g * 8);
    }
    CPC();
    issue_b(smb, 0, ch, tid);
    issue_b(smb, 1, ch, tid);    // NC >= 4 always when myT >= 1

    float sA[2][2], sP[2][2];
#pragma unroll
    for (int mi = 0; mi < 2; mi++)
#pragma unroll
        for (int h = 0; h < 2; h++) { sA[mi][h] = 0.f; sP[mi][h] = 0.f; }

#pragma unroll 1
    for (int tloc = 0; tloc < myT; tloc++) {
        float acc[2][4][4];
#pragma unroll
        for (int mi = 0; mi < 2; mi++)
#pragma unroll
            for (int n8 = 0; n8 < 4; n8++)
#pragma unroll
                for (int r = 0; r < 4; r++) acc[mi][n8][r] = 0.f;

#pragma unroll
        for (int kc = 0; kc < 4; kc++) {
            const int l = tloc * 4 + kc;
            if (l + 2 < NC) { issue_b(smb, l + 2, ch, tid); CPW2(); }
            else if (l + 2 == NC) { CPW1(); }
            else { CPW0(); }
            __syncthreads();
            if (kc == 0 && tid < BN)
                advT[tid] = g_cadv[(ch + 4 * tloc) * BN + tid];

            const uint32_t aC = smb + SM_A + (uint32_t)kc * 8192;
            const uint32_t bB = smb + SM_B + (uint32_t)(l & 3) * B_SLOT;
#pragma unroll
            for (int s = 0; s < 4; s++) {
                uint32_t af[2][4], bf[2][4];
#pragma unroll
                for (int mi = 0; mi < 2; mi++) {
                    uint32_t gr = (uint32_t)(((s * 2 + khA) ^ aRowX[mi]) << 4);
                    LDSM4(af[mi], aC + aRowByte[mi] + gr);
                }
#pragma unroll
                for (int nj = 0; nj < 2; nj++) {
                    uint32_t gr = (uint32_t)(((s * 2 + khB) ^ bRowX[nj]) << 4);
                    LDSM4(bf[nj], bB + bRowByte[nj] + gr);
                }
#pragma unroll
                for (int mi = 0; mi < 2; mi++)
#pragma unroll
                    for (int n8 = 0; n8 < 4; n8++)
                        MMA16816(acc[mi][n8], af[mi],
                                 bf[n8 >> 1][(n8 & 1) * 2],
                                 bf[n8 >> 1][(n8 & 1) * 2 + 1]);
            }
        }

        // ---- epilogue (32 EX2/thread) ----
#pragma unroll
        for (int n8 = 0; n8 < 4; n8++) {
            const int nb = wn * 32 + n8 * 8 + (lane & 3) * 2;
            const int a0 = advT[nb], a1 = advT[nb + 1];
#pragma unroll
            for (int mi = 0; mi < 2; mi++)
#pragma unroll
                for (int h = 0; h < 2; h++) {
                    float e0 = fast_exp2(acc[mi][n8][h * 2]);
                    float e1 = fast_exp2(acc[mi][n8][h * 2 + 1]);
                    if (a0 >= 0) sA[mi][h] += e0;
                    if (a1 >= 0) sA[mi][h] += e1;
                    if (a0 == adiR[mi][h]) sP[mi][h] += e0;
                    if (a1 == adiR[mi][h]) sP[mi][h] += e1;
                }
        }
    }

    // ---- reduce over lane&3, then across wn warps ----
#pragma unroll
    for (int mi = 0; mi < 2; mi++)
#pragma unroll
        for (int h = 0; h < 2; h++) {
#pragma unroll
            for (int o = 1; o < 4; o <<= 1) {
                sA[mi][h] += __shfl_xor_sync(0xffffffffu, sA[mi][h], o);
                sP[mi][h] += __shfl_xor_sync(0xffffffffu, sP[mi][h], o);
            }
        }
    if ((lane & 3) == 0) {
#pragma unroll
        for (int mi = 0; mi < 2; mi++)
#pragma unroll
            for (int h = 0; h < 2; h++) {
                int rl = wm * 32 + mi * 16 + h * 8 + (lane >> 2);
                redA[wn * 64 + rl] = sA[mi][h];
                redP[wn * 64 + rl] = sP[mi][h];
            }
    }
    __syncthreads();
    if (tid < BM) {
        float A = redA[tid] + redA[64 + tid] + redA[128 + tid] + redA[192 + tid];
        float P = redP[tid] + redP[64 + tid] + redP[128 + tid] + redP[192 + tid];
        g_rowAP[(size_t)(brow + tid) * 8 + ch] = A;
        g_rowAP[(size_t)(brow + tid) * 8 + 4 + ch] = P;
    }
}

// ---------------- kernel 4: finalize (vectorized row reduce) -----------------
__global__ void finalize_kernel(float* __restrict__ out) {
    const int t = threadIdx.x;   // 1024
    const int cnt = g_cnt;
    float l = 0.f;
#pragma unroll
    for (int i = 0; i < 8; i++) {
        int j = i * 1024 + t;
        if (j < cnt) {
            float4 a = *reinterpret_cast<const float4*>(g_rowAP + (size_t)j * 8);
            float4 p = *reinterpret_cast<const float4*>(g_rowAP + (size_t)j * 8 + 4);
            float A = (a.x + a.y) + (a.z + a.w);
            float P = (p.x + p.y) + (p.z + p.w);
            l += (log2f(A) - log2f(P)) * LN2F;
        }
    }
#pragma unroll
    for (int o = 16; o; o >>= 1) l += __shfl_xor_sync(0xffffffffu, l, o);
    __shared__ float sl[32];
    if ((t & 31) == 0) sl[t >> 5] = l;
    __syncthreads();
    if (t < 32) {
        l = sl[t];
#pragma unroll
        for (int o = 16; o; o >>= 1) l += __shfl_xor_sync(0xffffffffu, l, o);
        if (t == 0) out[0] = l / fmaxf((float)cnt, 1.0f);
    }
}

// ---------------- launch ------------------------------------------------------
extern "C" void kernel_launch(void* const* d_in, const int* in_sizes, int n_in,
                              void* d_out, int out_size) {
    const float* logits = (const float*)d_in[0];
    const float* labels = (const float*)d_in[1];
    const int*   pad    = (const int*)d_in[2];
    const int*   ad     = (const int*)d_in[3];

    cudaFuncSetAttribute(main_kernel, cudaFuncAttributeMaxDynamicSharedMemorySize,
                         DSMEM_BYTES);

    scan_kernel<<<1, 1024>>>(pad);
    scatter_kernel<<<dim3(1024, 2), 256>>>(logits, labels, ad);
    main_kernel<<<512, 256, DSMEM_BYTES>>>();
    finalize_kernel<<<1, 1024>>>((float*)d_out);
}